// round 9
// baseline (speedup 1.0000x reference)
#include <cuda_runtime.h>

#define T_BINS 151
#define TILE   64
#define PADW   132          // 128 + 4 floats pad: float4-aligned

// Global accumulators: [0..150] pos hist, [151..301] neg hist, [302] pos count.
// Zero at module load; the LAST block of every launch re-zeroes them after
// computing the loss -> every replay starts from zero (capture-safe).
__device__ float        g_hist[2 * T_BINS + 1];
__device__ unsigned int g_done;

// Packed dual-fp32 FMA: d.lo += a.lo*b.lo ; d.hi += a.hi*b.hi  (one instr).
// ptxas never auto-generates FFMA2; PTX fma.rn.f32x2 is the only route.
__device__ __forceinline__ void fma2(unsigned long long& d,
                                     unsigned long long a,
                                     unsigned long long b)
{
    asm("fma.rn.f32x2 %0, %1, %2, %3;" : "=l"(d) : "l"(a), "l"(b), "l"(d));
}

__device__ __forceinline__ float unpack_sum(unsigned long long x)
{
    float lo = __uint_as_float((unsigned int)x);
    float hi = __uint_as_float((unsigned int)(x >> 32));
    return lo + hi;
}

__global__ __launch_bounds__(512) void hist_loss_kernel(
    const float* __restrict__ feats, const int* __restrict__ cls,
    float* __restrict__ out, int N, int NT, int nblocks)
{
    extern __shared__ float sm[];
    float* As   = sm;                         // TILE x PADW
    float* Bs   = As + TILE * PADW;           // TILE x PADW
    float* hist = Bs + TILE * PADW;           // 2 * T_BINS
    int*   clsA = (int*)(hist + 2 * T_BINS);  // TILE
    int*   clsB = clsA + TILE;                // TILE
    int*   sPos = clsB + TILE;                // 1

    // Per-bin constants (pure functions of integer bin j), reference-bit-exact:
    __shared__ float t_lo[T_BINS];
    __shared__ float t_hi[T_BINS];
    __shared__ int   allow[T_BINS];
    __shared__ unsigned int s_ticket;

    const int tid = threadIdx.x;
    const float step     = (float)(2.0 / 150.0);
    const float inv_step = __fdiv_rn(1.0f, step);

    // Decode linear block id -> upper-triangular tile (bi, bj), bi <= bj.
    int k = blockIdx.x, bi = 0;
    while (k >= NT - bi) { k -= NT - bi; ++bi; }
    const int bj = bi + k;
    const bool diag = (bi == bj);

    for (int i = tid; i < 2 * T_BINS; i += 512) hist[i] = 0.0f;
    if (tid == 0) *sPos = 0;
    if (tid < TILE) {
        int gi = bi * TILE + tid;
        clsA[tid] = (gi < N) ? cls[gi] : -1;
        int gj = bj * TILE + tid;
        clsB[tid] = (gj < N) ? cls[gj] : -2;
    }
    if (tid < T_BINS) {
        float qf = (float)tid;
        float d  = __fsub_rn(__fmul_rn(qf, step), 1.0f);
        float t1 = __fadd_rn(-1.0f, __fmul_rn(__fadd_rn(qf, 1.0f), step));
        t_lo[tid]  = d;
        t_hi[tid]  = t1;
        allow[tid] = (d == __fsub_rn(t1, step));
    }

    // Load both feature tiles (64 rows x 128 floats) as float4, coalesced.
    const float4* f4 = (const float4*)feats;
    for (int idx = tid; idx < TILE * 32; idx += 512) {
        int r = idx >> 5, c = idx & 31;
        int gi = bi * TILE + r;
        float4 va = (gi < N) ? f4[gi * 32 + c] : make_float4(0.f, 0.f, 0.f, 0.f);
        *(float4*)(As + r * PADW + c * 4) = va;
        int gj = bj * TILE + r;
        float4 vb = (gj < N) ? f4[gj * 32 + c] : make_float4(0.f, 0.f, 0.f, 0.f);
        *(float4*)(Bs + r * PADW + c * 4) = vb;
    }
    __syncthreads();

    // 2x4 micro-tile: rows {tr, tr+32}, cols {tc+16v}. 512 thr x 8 out = 64x64.
    const int tr = tid >> 4;   // 0..31
    const int tc = tid & 15;   // 0..15

    // Packed accumulators: lane.lo sums even-k, lane.hi sums odd-k.
    unsigned long long acc[2][4];
#pragma unroll
    for (int u = 0; u < 2; ++u)
#pragma unroll
        for (int v = 0; v < 4; ++v) acc[u][v] = 0ull;

    for (int kk = 0; kk < 128; kk += 4) {
        ulonglong2 a[2], b[4];   // each = one LDS.128 = k..k+3 packed as 2 f32x2
#pragma unroll
        for (int u = 0; u < 2; ++u)
            a[u] = *(const ulonglong2*)(As + (tr + 32 * u) * PADW + kk);
#pragma unroll
        for (int v = 0; v < 4; ++v)
            b[v] = *(const ulonglong2*)(Bs + (tc + 16 * v) * PADW + kk);
#pragma unroll
        for (int u = 0; u < 2; ++u)
#pragma unroll
            for (int v = 0; v < 4; ++v) {
                fma2(acc[u][v], a[u].x, b[v].x);
                fma2(acc[u][v], a[u].y, b[v].y);
            }
    }

    // ---- Binning (reference fp32 semantics via per-bin tables) ----
    int localPos = 0;
#pragma unroll
    for (int u = 0; u < 2; ++u) {
#pragma unroll
        for (int v = 0; v < 4; ++v) {
            int ri = tr + 32 * u, rj = tc + 16 * v;
            if (!diag || ri < rj) {
                float s  = unpack_sum(acc[u][v]);
                float q  = floorf(__fmul_rn(__fadd_rn(s, 1.0f), inv_step));
                int   j0 = (int)q;
                bool  eq = (clsA[ri] == clsB[rj]);
                float* h = eq ? hist : (hist + T_BINS);
                if (eq) ++localPos;
                if (j0 >= 0 && j0 < T_BINS) {
                    float wb = __fmul_rn(
                        __fadd_rn(__fadd_rn(-s, t_lo[j0]), step), inv_step);
                    atomicAdd(&h[j0], wb);
                    if (j0 + 1 < T_BINS && allow[j0]) {
                        float wa = __fmul_rn(
                            __fadd_rn(__fsub_rn(s, t_hi[j0]), step), inv_step);
                        atomicAdd(&h[j0 + 1], wa);
                    }
                }
            }
        }
    }
    if (localPos) atomicAdd(sPos, localPos);
    __syncthreads();

    // Flush per-block shared histogram into the global accumulator (L2 atomics).
    for (int i = tid; i < 2 * T_BINS; i += 512) {
        float v = hist[i];
        if (v != 0.0f) atomicAdd(&g_hist[i], v);
    }
    if (tid == 0 && *sPos) atomicAdd(&g_hist[2 * T_BINS], (float)(*sPos));

    // ---- last-block-done finalize ----
    __threadfence();
    if (tid == 0) s_ticket = atomicInc(&g_done, 0xFFFFFFFFu);
    __syncthreads();
    if (s_ticket != (unsigned)(nblocks - 1)) return;
    __threadfence();

    float* hp  = hist;              // reuse shared memory
    float* hn  = hist + T_BINS;
    float* red = As;                // reuse tile A region (512 floats)
    __shared__ float s_inv_pos, s_inv_neg;

    float vp = 0.f, vn = 0.f;
    if (tid < T_BINS) {
        vp = __ldcg(&g_hist[tid]);
        vn = __ldcg(&g_hist[T_BINS + tid]);
    }
    if (tid == 0) {
        float cnt  = __ldcg(&g_hist[2 * T_BINS]);
        float Ptot = 0.5f * (float)N * (float)(N - 1);
        s_inv_pos = 1.0f / cnt;
        s_inv_neg = 1.0f / (Ptot - cnt);
    }
    __syncthreads();
    if (tid < T_BINS) {
        hp[tid] = vp * s_inv_pos;
        hn[tid] = vn * s_inv_neg;
    }
    __syncthreads();

    // inclusive scan of hp (Hillis-Steele, 8 steps)
    for (int off = 1; off < T_BINS; off <<= 1) {
        float v = (tid < T_BINS && tid >= off) ? hp[tid - off] : 0.f;
        __syncthreads();
        if (tid < T_BINS) hp[tid] += v;
        __syncthreads();
    }

    // dot(hn, cdf) via power-of-2 tree reduce over 512 slots
    red[tid] = (tid < T_BINS) ? hn[tid] * hp[tid] : 0.f;
    __syncthreads();
#pragma unroll
    for (int s = 256; s > 0; s >>= 1) {
        if (tid < s) red[tid] += red[tid + s];
        __syncthreads();
    }
    if (tid == 0) out[0] = red[0];

    // Reset globals for the next replay (invariant: zero at kernel entry).
    for (int i = tid; i < 2 * T_BINS + 1; i += 512) g_hist[i] = 0.0f;
    if (tid == 0) g_done = 0u;
}

extern "C" void kernel_launch(void* const* d_in, const int* in_sizes, int n_in,
                              void* d_out, int out_size)
{
    const float* feats = (const float*)d_in[0];
    const int*   cls   = (const int*)d_in[1];
    int N  = in_sizes[1];                 // classes element count = number of rows
    int NT = (N + TILE - 1) / TILE;
    int nblocks = NT * (NT + 1) / 2;      // 136 for N=1024

    size_t smem = (size_t)(2 * TILE * PADW + 2 * T_BINS) * sizeof(float)
                + (size_t)(2 * TILE + 4) * sizeof(int);
    cudaFuncSetAttribute(hist_loss_kernel,
                         cudaFuncAttributeMaxDynamicSharedMemorySize, (int)smem);

    hist_loss_kernel<<<nblocks, 512, smem>>>(feats, cls, (float*)d_out,
                                             N, NT, nblocks);
}

// round 10
// speedup vs baseline: 1.2183x; 1.2183x over previous
#include <cuda_runtime.h>

#define T_BINS 151
#define TILE   32
#define PADW   132          // 128 + 4 floats pad: float4-aligned
#define NREP   8            // histogram replicas (bank-spread for ATOMS)

// Global accumulators: [0..150] pos hist, [151..301] neg hist, [302] pos count.
// Zero at module load; the LAST block of every launch re-zeroes them after
// computing the loss -> every replay starts from zero (capture-safe).
__device__ float        g_hist[2 * T_BINS + 1];
__device__ unsigned int g_done;

// Packed dual-fp32 FMA (sm_103a FFMA2; only reachable via PTX).
__device__ __forceinline__ void fma2(unsigned long long& d,
                                     unsigned long long a,
                                     unsigned long long b)
{
    asm("fma.rn.f32x2 %0, %1, %2, %3;" : "=l"(d) : "l"(a), "l"(b), "l"(d));
}

__device__ __forceinline__ float unpack_sum(unsigned long long x)
{
    float lo = __uint_as_float((unsigned int)x);
    float hi = __uint_as_float((unsigned int)(x >> 32));
    return lo + hi;
}

__global__ __launch_bounds__(256) void hist_loss_kernel(
    const float* __restrict__ feats, const int* __restrict__ cls,
    float* __restrict__ out, int N, int NT, int nblocks)
{
    extern __shared__ float sm[];
    float* As    = sm;                          // TILE x PADW
    float* Bs    = As + TILE * PADW;            // TILE x PADW
    float* rhist = Bs + TILE * PADW;            // 2*T_BINS*NREP (replicated)
    int*   clsA  = (int*)(rhist + 2 * T_BINS * NREP);  // TILE
    int*   clsB  = clsA + TILE;                 // TILE
    int*   sPos  = clsB + TILE;                 // 1

    // Per-bin constants (pure functions of integer bin j), reference-bit-exact.
    __shared__ float t_lo[T_BINS];
    __shared__ float t_hi[T_BINS];
    __shared__ int   allow[T_BINS];
    __shared__ unsigned int s_ticket;

    const int tid = threadIdx.x;
    const float step     = (float)(2.0 / 150.0);
    const float inv_step = __fdiv_rn(1.0f, step);

    // Decode linear block id -> upper-triangular tile (bi, bj), bi <= bj.
    int k = blockIdx.x, bi = 0;
    while (k >= NT - bi) { k -= NT - bi; ++bi; }
    const int bj = bi + k;
    const bool diag = (bi == bj);

    for (int i = tid; i < 2 * T_BINS * NREP; i += 256) rhist[i] = 0.0f;
    if (tid == 0) *sPos = 0;
    if (tid < TILE) {
        int gi = bi * TILE + tid;
        clsA[tid] = (gi < N) ? cls[gi] : -1;
        int gj = bj * TILE + tid;
        clsB[tid] = (gj < N) ? cls[gj] : -2;
    }
    if (tid < T_BINS) {
        float qf = (float)tid;
        float d  = __fsub_rn(__fmul_rn(qf, step), 1.0f);
        float t1 = __fadd_rn(-1.0f, __fmul_rn(__fadd_rn(qf, 1.0f), step));
        t_lo[tid]  = d;
        t_hi[tid]  = t1;
        allow[tid] = (d == __fsub_rn(t1, step));
    }

    // Load both feature tiles (32 rows x 128 floats) as float4, coalesced.
    const float4* f4 = (const float4*)feats;
    for (int idx = tid; idx < TILE * 32; idx += 256) {
        int r = idx >> 5, c = idx & 31;
        int gi = bi * TILE + r;
        float4 va = (gi < N) ? f4[gi * 32 + c] : make_float4(0.f, 0.f, 0.f, 0.f);
        *(float4*)(As + r * PADW + c * 4) = va;
        int gj = bj * TILE + r;
        float4 vb = (gj < N) ? f4[gj * 32 + c] : make_float4(0.f, 0.f, 0.f, 0.f);
        *(float4*)(Bs + r * PADW + c * 4) = vb;
    }
    __syncthreads();

    // 2x2 micro-tile: 256 threads as 16x16; rows {tr,tr+16}, cols {tc,tc+16}.
    const int tr = tid >> 4;   // 0..15
    const int tc = tid & 15;   // 0..15

    unsigned long long acc[2][2];
#pragma unroll
    for (int u = 0; u < 2; ++u)
#pragma unroll
        for (int v = 0; v < 2; ++v) acc[u][v] = 0ull;

    for (int kk = 0; kk < 128; kk += 4) {
        ulonglong2 a[2], b[2];
#pragma unroll
        for (int u = 0; u < 2; ++u)
            a[u] = *(const ulonglong2*)(As + (tr + 16 * u) * PADW + kk);
#pragma unroll
        for (int v = 0; v < 2; ++v)
            b[v] = *(const ulonglong2*)(Bs + (tc + 16 * v) * PADW + kk);
#pragma unroll
        for (int u = 0; u < 2; ++u)
#pragma unroll
            for (int v = 0; v < 2; ++v) {
                fma2(acc[u][v], a[u].x, b[v].x);
                fma2(acc[u][v], a[u].y, b[v].y);
            }
    }

    // ---- Binning (reference fp32 semantics via per-bin tables) ----
    // Replicated hist: slot = ((bin*2 + neg)*NREP + rep), rep = lane&7.
    // Lanes sharing a bin hit 8 consecutive banks -> ~8x less serialization.
    const int rep = tid & (NREP - 1);
    int localPos = 0;
#pragma unroll
    for (int u = 0; u < 2; ++u) {
#pragma unroll
        for (int v = 0; v < 2; ++v) {
            int ri = tr + 16 * u, rj = tc + 16 * v;
            if (!diag || ri < rj) {
                float s  = unpack_sum(acc[u][v]);
                float q  = floorf(__fmul_rn(__fadd_rn(s, 1.0f), inv_step));
                int   j0 = (int)q;
                int   ng = (clsA[ri] == clsB[rj]) ? 0 : 1;
                if (!ng) ++localPos;
                if (j0 >= 0 && j0 < T_BINS) {
                    float wb = __fmul_rn(
                        __fadd_rn(__fadd_rn(-s, t_lo[j0]), step), inv_step);
                    atomicAdd(&rhist[((j0 * 2 + ng) * NREP) + rep], wb);
                    if (j0 + 1 < T_BINS && allow[j0]) {
                        float wa = __fmul_rn(
                            __fadd_rn(__fsub_rn(s, t_hi[j0]), step), inv_step);
                        atomicAdd(&rhist[(((j0 + 1) * 2 + ng) * NREP) + rep], wa);
                    }
                }
            }
        }
    }
    if (localPos) atomicAdd(sPos, localPos);
    __syncthreads();

    // Merge replicas and flush into the global accumulator (L2 atomics).
    // g_hist layout: [0..150] pos, [151..301] neg.
    for (int i = tid; i < 2 * T_BINS; i += 256) {
        int bin = (i < T_BINS) ? i : (i - T_BINS);
        int ng  = (i < T_BINS) ? 0 : 1;
        const float* src = &rhist[(bin * 2 + ng) * NREP];
        float v = 0.f;
#pragma unroll
        for (int r = 0; r < NREP; ++r) v += src[r];
        if (v != 0.0f) atomicAdd(&g_hist[i], v);
    }
    if (tid == 0 && *sPos) atomicAdd(&g_hist[2 * T_BINS], (float)(*sPos));

    // ---- last-block-done finalize ----
    __threadfence();
    if (tid == 0) s_ticket = atomicInc(&g_done, 0xFFFFFFFFu);
    __syncthreads();
    if (s_ticket != (unsigned)(nblocks - 1)) return;
    __threadfence();

    float* hp  = rhist;             // reuse shared memory
    float* hn  = rhist + T_BINS;
    float* red = As;                // reuse tile A region (256 floats)
    __shared__ float s_inv_pos, s_inv_neg;

    float vp = 0.f, vn = 0.f;
    if (tid < T_BINS) {
        vp = __ldcg(&g_hist[tid]);
        vn = __ldcg(&g_hist[T_BINS + tid]);
    }
    if (tid == 0) {
        float cnt  = __ldcg(&g_hist[2 * T_BINS]);
        float Ptot = 0.5f * (float)N * (float)(N - 1);
        s_inv_pos = 1.0f / cnt;
        s_inv_neg = 1.0f / (Ptot - cnt);
    }
    __syncthreads();
    if (tid < T_BINS) {
        hp[tid] = vp * s_inv_pos;
        hn[tid] = vn * s_inv_neg;
    }
    __syncthreads();

    // inclusive scan of hp (Hillis-Steele, 8 steps)
    for (int off = 1; off < T_BINS; off <<= 1) {
        float v = (tid < T_BINS && tid >= off) ? hp[tid - off] : 0.f;
        __syncthreads();
        if (tid < T_BINS) hp[tid] += v;
        __syncthreads();
    }

    // dot(hn, cdf) via power-of-2 tree reduce over 256 slots
    red[tid] = (tid < T_BINS) ? hn[tid] * hp[tid] : 0.f;
    __syncthreads();
#pragma unroll
    for (int s = 128; s > 0; s >>= 1) {
        if (tid < s) red[tid] += red[tid + s];
        __syncthreads();
    }
    if (tid == 0) out[0] = red[0];

    // Reset globals for the next replay (invariant: zero at kernel entry).
    for (int i = tid; i < 2 * T_BINS + 1; i += 256) g_hist[i] = 0.0f;
    if (tid == 0) g_done = 0u;
}

extern "C" void kernel_launch(void* const* d_in, const int* in_sizes, int n_in,
                              void* d_out, int out_size)
{
    const float* feats = (const float*)d_in[0];
    const int*   cls   = (const int*)d_in[1];
    int N  = in_sizes[1];                 // classes element count = number of rows
    int NT = (N + TILE - 1) / TILE;
    int nblocks = NT * (NT + 1) / 2;      // 528 for N=1024

    size_t smem = (size_t)(2 * TILE * PADW + 2 * T_BINS * NREP) * sizeof(float)
                + (size_t)(2 * TILE + 4) * sizeof(int);
    cudaFuncSetAttribute(hist_loss_kernel,
                         cudaFuncAttributeMaxDynamicSharedMemorySize, (int)smem);

    hist_loss_kernel<<<nblocks, 256, smem>>>(feats, cls, (float*)d_out,
                                             N, NT, nblocks);
}